// round 11
// baseline (speedup 1.0000x reference)
#include <cuda_runtime.h>
#include <cuda_bf16.h>
#include <cstdint>

// ---------------------------------------------------------------------------
// YOLOv2 decode + greedy per-class NMS (exact sorted-walk equivalence).
// R11: pipeline decomposition. decode(+hist) -> cutoff -> gather -> nms_walk.
// Each phase runs at its natural width instead of one 64-CTA mega-kernel.
// ---------------------------------------------------------------------------

static constexpr int Bn = 64;
static constexpr int Hn = 40;
static constexpr int Wn = 40;
static constexpr int An = 5;
static constexpr int Cn = 80;
static constexpr int NPB = Hn * Wn * An;      // 8000
static constexpr int NBOX = Bn * NPB;         // 512000
static constexpr int MAXB = 100;
static constexpr int NBIN = 4096;             // fine bins: (key>>36) - (117<<8)
static constexpr int BINBASE = 117 << 8;
static constexpr int TARGET = 192;
static constexpr int WCAP = 1024;
static constexpr float SCORE_THR = 0.001f;
static constexpr float IOU_THR = 0.5f;

__device__ unsigned long long g_keys[NBOX];
__device__ unsigned int g_hist[Bn * NBIN];            // zero at load; cutoff re-zeroes
__device__ unsigned long long g_win[Bn * WCAP];
__device__ int g_wcnt[Bn];                            // zero at load; nms_walk re-zeroes
__device__ int g_cut[Bn];
__device__ int g_total[Bn];

// ---------------------------------------------------------------------------
// Decode: 512 thr/block, four threads per box; writes keys + fine histogram.
// ---------------------------------------------------------------------------
__global__ __launch_bounds__(512, 3) void decode_kernel(
    const float* __restrict__ pred)
{
    __shared__ __align__(16) float s[128 * 85];
    const int tid = threadIdx.x;
    const unsigned FULL = 0xffffffffu;

    {
        const float4* src = (const float4*)pred + (long long)blockIdx.x * 2720;
        float4* dst = (float4*)s;
        #pragma unroll
        for (int i = 0; i < 5; ++i)
            dst[tid + i * 512] = src[tid + i * 512];
        if (tid < 160) dst[tid + 2560] = src[tid + 2560];
    }
    __syncthreads();

    const int boxl = tid >> 2;
    const int q    = tid & 3;
    const float* p = s + boxl * 85;
    const int jb = 5 + q * 20;

    float bv = p[jb];
    int   bc = jb - 5;
    #pragma unroll 4
    for (int j = jb + 1; j < jb + 20; ++j) {
        float v = p[j];
        if (v > bv) { bv = v; bc = j - 5; }
    }
    #pragma unroll
    for (int o = 1; o <= 2; o <<= 1) {
        float obv = __shfl_xor_sync(FULL, bv, o);
        int   obc = __shfl_xor_sync(FULL, bc, o);
        if (obv > bv || (obv == bv && obc < bc)) { bv = obv; bc = obc; }
    }

    float a0 = 0.f, a1 = 0.f;
    #pragma unroll 4
    for (int j = jb; j < jb + 20; j += 2) {
        a0 += expf(p[j]     - bv);
        a1 += expf(p[j + 1] - bv);
    }
    float se = a0 + a1;
    #pragma unroll
    for (int o = 1; o <= 2; o <<= 1)
        se += __shfl_xor_sync(FULL, se, o);

    if (q == 0) {
        const int box = blockIdx.x * 128 + boxl;
        const int n   = box % NPB;
        const int b   = box / NPB;
        float conf  = 1.0f / (1.0f + expf(-p[4]));
        float score = conf / se;

        unsigned long long key = 0ull;
        if (score > SCORE_THR) {
            key = ((unsigned long long)__float_as_uint(score) << 21)
                | ((unsigned long long)(unsigned)(8191 - n) << 8)
                | (unsigned long long)(unsigned)bc;
            int bin = (int)(key >> 36) - BINBASE;      // in [0, 4096)
            atomicAdd(&g_hist[b * NBIN + bin], 1u);
        }
        g_keys[box] = key;
    }
}

// ---------------------------------------------------------------------------
// Cutoff: 64 blocks x 128 thr. Suffix stats over 4096 bins; pick largest bin
// with >= TARGET keys above it; re-zero hist for next replay.
// ---------------------------------------------------------------------------
__global__ __launch_bounds__(128) void cutoff_kernel()
{
    __shared__ unsigned wtot[4];
    __shared__ int s_best;

    const int b    = blockIdx.x;
    const int tid  = threadIdx.x;
    const int lane = tid & 31;
    const int wid  = tid >> 5;
    const unsigned FULL = 0xffffffffu;
    const int base = tid * 32;
    unsigned* h = g_hist + b * NBIN;

    unsigned tot = 0;
    #pragma unroll 8
    for (int i = 0; i < 32; ++i) tot += h[base + i];

    // warp inclusive suffix of per-thread totals (higher lane = higher bins)
    unsigned suf = tot;
    #pragma unroll
    for (int o = 1; o < 32; o <<= 1) {
        unsigned v = __shfl_down_sync(FULL, suf, o);
        if (lane + o < 32) suf += v;
    }
    if (lane == 0) wtot[wid] = suf;
    if (tid == 0) s_best = 0;
    __syncthreads();

    unsigned above_warp = 0;
    for (int w = wid + 1; w < 4; ++w) above_warp += wtot[w];
    unsigned above_thread = above_warp + (suf - tot);

    if (tid == 0) g_total[b] = (int)(above_thread + tot);

    // pass2: running suffix within my 32 bins, high->low; first hit = best here
    unsigned run = above_thread;
    int best = -1;
    for (int i = 31; i >= 0; --i) {
        run += h[base + i];
        if (run >= (unsigned)TARGET) { best = base + i; break; }
    }
    if (best > 0) atomicMax(&s_best, best);

    // zero my hist range (after pass2 reads)
    #pragma unroll 8
    for (int i = 0; i < 32; ++i) h[base + i] = 0u;

    __syncthreads();
    if (tid == 0) g_cut[b] = s_best;
}

// ---------------------------------------------------------------------------
// Gather: 256 blocks x 256 thr (4 CTAs per image). Compact keys with
// bin >= cut[b] into g_win[b] via warp-aggregated global atomics.
// ---------------------------------------------------------------------------
__global__ __launch_bounds__(256) void gather_kernel()
{
    const int cta  = blockIdx.x;
    const int b    = cta >> 2;
    const int part = cta & 3;
    const int tid  = threadIdx.x;
    const int lane = tid & 31;
    const unsigned FULL = 0xffffffffu;
    const int cut  = g_cut[b];

    const int lo = part * 2000, hi = lo + 2000;
    for (int i = lo + tid; i < hi; i += 256) {
        unsigned long long k = g_keys[b * NPB + i];
        bool take = (k != 0ull) && ((int)(k >> 36) - BINBASE >= cut);
        unsigned msk = __ballot_sync(FULL, take);
        int basep = 0;
        if (lane == 0 && msk) basep = atomicAdd(&g_wcnt[b], __popc(msk));
        basep = __shfl_sync(FULL, basep, 0);
        if (take) {
            int ofs = basep + __popc(msk & ((1u << lane) - 1u));
            if (ofs < WCAP) g_win[b * WCAP + ofs] = k;
        }
    }
}

// ---------------------------------------------------------------------------
// Helpers for nms_walk
// ---------------------------------------------------------------------------
__device__ __forceinline__ float iou_(float4 a, float4 b) {
    float xx1 = fmaxf(a.x, b.x), yy1 = fmaxf(a.y, b.y);
    float xx2 = fminf(a.z, b.z), yy2 = fminf(a.w, b.w);
    float inter = fmaxf(xx2 - xx1, 0.0f) * fmaxf(yy2 - yy1, 0.0f);
    float aa = fmaxf(a.z - a.x, 0.0f) * fmaxf(a.w - a.y, 0.0f);
    float ab = fmaxf(b.z - b.x, 0.0f) * fmaxf(b.w - b.y, 0.0f);
    return inter / (aa + ab - inter + 1e-8f);
}

__device__ __forceinline__ float4 decode_box_(
    const float* __restrict__ pred, const float* __restrict__ anch,
    int b, int n)
{
    const float* pp = pred + ((long long)b * NPB + n) * 85;
    float t0 = pp[0], t1 = pp[1], t2 = pp[2], t3 = pp[3];
    int a  = n % An;
    int hw = n / An;
    float gy = (float)(hw / Wn);
    float gx = (float)(hw % Wn);
    float sx = 1.0f / (1.0f + expf(-t0));
    float sy = 1.0f / (1.0f + expf(-t1));
    float cx = (sx + gx) / 40.0f;
    float cy = (sy + gy) / 40.0f;
    float bw = (expf(t2) * anch[2 * a])     / 40.0f;
    float bh = (expf(t3) * anch[2 * a + 1]) / 40.0f;
    return make_float4(cx - 0.5f * bw, cy - 0.5f * bh,
                       cx + 0.5f * bw, cy + 0.5f * bh);
}

// ---------------------------------------------------------------------------
// NMS walk: 64 blocks x 256 thr. Rank-sort window, class-decomposed greedy
// (8 warps x 10 classes), ordered output. Exact argmax-walk fallback.
// ---------------------------------------------------------------------------
__global__ __launch_bounds__(256) void nms_walk_kernel(
    float* __restrict__ out,
    const float* __restrict__ pred, const float* __restrict__ anch)
{
    __shared__ unsigned long long buf[WCAP];
    __shared__ unsigned long long buf2[WCAP];
    __shared__ __align__(16) float4 sbox[WCAP];
    __shared__ float4 abox[MAXB];
    __shared__ int    acls[MAXB];
    __shared__ unsigned sbm[WCAP / 32];
    __shared__ int    sh_count, sh_overflow;
    __shared__ unsigned long long sh_maxkey;
    __shared__ unsigned procbm[NPB / 32];      // fallback processed bitmap

    const int b    = blockIdx.x;
    const int tid  = threadIdx.x;
    const int lane = tid & 31;
    const int wid  = tid >> 5;
    const unsigned FULL = 0xffffffffu;

    const int wcnt  = g_wcnt[b];
    const int cut   = g_cut[b];
    const int total = g_total[b];
    if (tid == 0) { g_wcnt[b] = 0; sh_count = 0; sh_overflow = 0; }

    float* out_boxes = out;
    float* out_score = out + (long long)Bn * MAXB * 4;
    float* out_class = out + (long long)Bn * MAXB * 5;

    bool need_fallback = (wcnt > WCAP);
    const int cnt = need_fallback ? 0 : wcnt;

    if (!need_fallback && cnt > 0) {
        for (int i = tid; i < cnt; i += 256) buf[i] = g_win[b * WCAP + i];
        for (int i = tid; i < WCAP / 32; i += 256) sbm[i] = 0u;
        __syncthreads();

        // rank-sort descending (keys unique)
        for (int i = tid; i < cnt; i += 256) {
            unsigned long long ki = buf[i];
            int r = 0;
            for (int j = 0; j < cnt; ++j) r += (buf[j] > ki);
            buf2[r] = ki;
        }
        __syncthreads();

        // lazy box decode for sorted candidates
        for (int i = tid; i < cnt; i += 256) {
            int n = 8191 - (int)((buf2[i] >> 8) & 0x1FFFu);
            sbox[i] = decode_box_(pred, anch, b, n);
        }
        __syncthreads();

        // class-decomposed greedy: warp w owns classes w, w+8, ..., w+72
        for (int c = wid; c < Cn; c += 8) {
            float4 acc0, acc1;
            int na = 0;
            for (int base = 0; base < cnt; base += 32) {
                int i = base + lane;
                bool mine = (i < cnt) && ((int)(buf2[i] & 0xFFu) == c);
                unsigned mk = __ballot_sync(FULL, mine);
                while (mk) {
                    int i2 = base + (__ffs(mk) - 1);
                    mk &= mk - 1;
                    float4 bx = sbox[i2];
                    bool hit = false;
                    if (lane < na)      hit  = iou_(acc0, bx) > IOU_THR;
                    if (32 + lane < na) hit |= iou_(acc1, bx) > IOU_THR;
                    if (!__any_sync(FULL, hit)) {
                        if (na < 64) {
                            if (lane == (na & 31)) {
                                if (na < 32) acc0 = bx; else acc1 = bx;
                            }
                            if (lane == 0)
                                atomicOr(&sbm[i2 >> 5], 1u << (i2 & 31));
                        } else {
                            if (lane == 0) sh_overflow = 1;
                        }
                        ++na;
                    }
                }
            }
        }
        __syncthreads();

        if (!sh_overflow) {
            // in-order survivor compaction (warp 0)
            if (tid < 32) {
                int c = 0;
                for (int w = 0; w < WCAP / 32 && c < MAXB; ++w) {
                    unsigned bits = sbm[w];
                    bool set = (bits >> lane) & 1u;
                    int rank = __popc(bits & ((1u << lane) - 1u));
                    int slot = c + rank;
                    if (set && slot < MAXB) {
                        int i2 = w * 32 + lane;
                        unsigned long long key = buf2[i2];
                        float4 bx = sbox[i2];
                        abox[slot] = bx;
                        acls[slot] = (int)(key & 0xFFu);
                        long long o = (long long)b * MAXB + slot;
                        out_boxes[o * 4 + 0] = bx.x;
                        out_boxes[o * 4 + 1] = bx.y;
                        out_boxes[o * 4 + 2] = bx.z;
                        out_boxes[o * 4 + 3] = bx.w;
                        out_score[o] = __uint_as_float((unsigned)(key >> 21));
                        out_class[o] = (float)(key & 0xFFu);
                    }
                    c = min(c + __popc(bits), MAXB);
                }
                if (lane == 0) sh_count = c;
            }
        } else {
            need_fallback = true;
        }
        __syncthreads();
        // window incomplete (cut>0 means keys exist below the window)
        if (!need_fallback && sh_count < MAXB && cut > 0 && wcnt < total)
            need_fallback = true;
    }

    // -------- exact fallback: repeated argmax walk over all keys (rare) ----
    if (need_fallback) {
        __syncthreads();
        if (tid == 0) sh_count = 0;
        for (int i = tid; i < NPB / 32; i += 256) procbm[i] = 0u;
        __syncthreads();

        while (true) {
            if (tid == 0) sh_maxkey = 0ull;
            __syncthreads();
            unsigned long long mk = 0ull;
            for (int i = tid; i < NPB; i += 256) {
                if (!((procbm[i >> 5] >> (i & 31)) & 1u)) {
                    unsigned long long k = g_keys[b * NPB + i];
                    if (k > mk) mk = k;
                }
            }
            // block max
            #pragma unroll
            for (int o = 16; o; o >>= 1) {
                unsigned long long v = __shfl_xor_sync(FULL, mk, o);
                if (v > mk) mk = v;
            }
            if (lane == 0) atomicMax(&sh_maxkey, mk);
            __syncthreads();
            unsigned long long key = sh_maxkey;
            if (key == 0ull || sh_count >= MAXB) break;

            int n   = 8191 - (int)((key >> 8) & 0x1FFFu);
            int cls = (int)(key & 0xFFu);
            if (tid == 0) procbm[n >> 5] |= 1u << (n & 31);

            float4 bx = decode_box_(pred, anch, b, n);
            bool rej = false;
            int c = sh_count;
            for (int j = tid; j < c; j += 256)
                if (acls[j] == cls && iou_(abox[j], bx) > IOU_THR) rej = true;
            if (__syncthreads_or(rej ? 1 : 0) == 0) {
                if (tid == 0) {
                    abox[c] = bx;
                    acls[c] = cls;
                    long long o = (long long)b * MAXB + c;
                    out_boxes[o * 4 + 0] = bx.x;
                    out_boxes[o * 4 + 1] = bx.y;
                    out_boxes[o * 4 + 2] = bx.z;
                    out_boxes[o * 4 + 3] = bx.w;
                    out_score[o] = __uint_as_float((unsigned)(key >> 21));
                    out_class[o] = (float)cls;
                    sh_count = c + 1;
                }
            }
            __syncthreads();
        }
    }
    __syncthreads();

    int cntf = sh_count;
    for (int j = tid; j < MAXB; j += 256) {
        if (j >= cntf) {
            long long o = (long long)b * MAXB + j;
            out_boxes[o * 4 + 0] = 0.0f;
            out_boxes[o * 4 + 1] = 0.0f;
            out_boxes[o * 4 + 2] = 0.0f;
            out_boxes[o * 4 + 3] = 0.0f;
            out_score[o] = 0.0f;
            out_class[o] = -1.0f;
        }
    }
}

extern "C" void kernel_launch(void* const* d_in, const int* in_sizes, int n_in,
                              void* d_out, int out_size)
{
    const float* pred = (const float*)d_in[0];
    const float* anch = (const float*)d_in[1];
    float* out = (float*)d_out;

    decode_kernel<<<NBOX / 128, 512>>>(pred);
    cutoff_kernel<<<Bn, 128>>>();
    gather_kernel<<<Bn * 4, 256>>>();
    nms_walk_kernel<<<Bn, 256>>>(out, pred, anch);
}